// round 11
// baseline (speedup 1.0000x reference)
#include <cuda_runtime.h>

#define NN 50000
#define NE 800000
#define H 128
#define ED 32
#define BN_EPS 1e-5f
#define RES_SCALE 0.1f

// ---------------- scratch (device globals; allocation-free) ----------------
__device__ __align__(16) float g_h[NN * H];
__device__ __align__(16) float g_z[NN * H];
__device__ __align__(16) float g_t[NN * H];
__device__ __align__(16) float g_z2[NN * H];
__device__ __align__(16) float g_eas[(size_t)NE * ED];  // ea in CSR order
__device__ int g_src[NE];
__device__ int g_dstv[NE];
__device__ int g_ssort[NE];
__device__ int g_dsort[NE];
__device__ int g_cnt[NN];
__device__ int g_cursor[NN];
__device__ int g_bsum[64];
__device__ __align__(16) float g_colsum[H];
__device__ __align__(16) float g_colsq[H];
__device__ __align__(16) float g_scale[H];
__device__ __align__(16) float g_shift[H];

__device__ __forceinline__ unsigned to_tf32(float f) {
    unsigned u;
    asm("cvt.rna.tf32.f32 %0, %1;" : "=r"(u) : "f"(f));
    return u;
}

// split fp32 into tf32 hi + tf32 lo (3xTF32 scheme)
__device__ __forceinline__ void split_tf32(float v, unsigned& hi, unsigned& lo) {
    unsigned h;
    asm("cvt.rna.tf32.f32 %0, %1;" : "=r"(h) : "f"(v));
    float hf = __uint_as_float(h);
    float l = v - hf;
    asm("cvt.rna.tf32.f32 %0, %1;" : "=r"(lo) : "f"(l));
    hi = h;
}

#define MMA_TF32(D, A0, A1, A2, A3, B0, B1)                                   \
    asm("mma.sync.aligned.m16n8k8.row.col.f32.tf32.tf32.f32 "                 \
        "{%0,%1,%2,%3}, {%4,%5,%6,%7}, {%8,%9}, {%0,%1,%2,%3};"               \
        : "+f"(D[0]), "+f"(D[1]), "+f"(D[2]), "+f"(D[3])                      \
        : "r"(A0), "r"(A1), "r"(A2), "r"(A3), "r"(B0), "r"(B1))

// ---------------- init: h = z = x, zero counts ----------------
__global__ void k_init(const float* __restrict__ x) {
    int i = blockIdx.x * blockDim.x + threadIdx.x;
    if (i < NN * H) {
        float v = x[i];
        g_h[i] = v;
        g_z[i] = v;
    }
    if (i < NN) g_cnt[i] = 0;
}

// ---------------- CSR build (detect int64 vs int32 in-warp) ----------------
__global__ void k_prep(const int* __restrict__ p) {
    int lane = threadIdx.x & 31;
    int hi = p[2 * lane + 1] | p[2 * (lane + 32) + 1];
    bool i64 = (__ballot_sync(0xffffffffu, hi != 0) == 0);
    int e = blockIdx.x * blockDim.x + threadIdx.x;
    if (e >= NE) return;
    int s, d;
    if (i64) {
        const long long* q = (const long long*)p;
        s = (int)q[e];
        d = (int)q[NE + e];
    } else {
        s = p[e];
        d = p[NE + e];
    }
    g_src[e] = s;
    g_dstv[e] = d;
    atomicAdd(&g_cnt[d], 1);
}

// hierarchical scan: A) per-block sums, BC) scan of sums + per-block scan
__global__ void k_scanA() {
    __shared__ int ws[32];
    int tid = threadIdx.x, lane = tid & 31, wid = tid >> 5;
    int i = blockIdx.x * 1024 + tid;
    int v = (i < NN) ? g_cnt[i] : 0;
    int s = v;
#pragma unroll
    for (int o = 16; o > 0; o >>= 1) s += __shfl_down_sync(0xffffffffu, s, o);
    if (lane == 0) ws[wid] = s;
    __syncthreads();
    if (wid == 0) {
        int t = ws[lane];
#pragma unroll
        for (int o = 16; o > 0; o >>= 1) t += __shfl_down_sync(0xffffffffu, t, o);
        if (lane == 0) g_bsum[blockIdx.x] = t;
    }
}

__global__ void k_scanBC(int nblk) {
    __shared__ int ws[32];
    __shared__ int boff_s;
    int tid = threadIdx.x, lane = tid & 31, wid = tid >> 5;
    if (wid == 0) {
        int v0 = (lane < nblk) ? g_bsum[lane] : 0;
        int v1 = (lane + 32 < nblk) ? g_bsum[lane + 32] : 0;
        int s0 = v0;
#pragma unroll
        for (int o = 1; o < 32; o <<= 1) {
            int t = __shfl_up_sync(0xffffffffu, s0, o);
            if (lane >= o) s0 += t;
        }
        int tot0 = __shfl_sync(0xffffffffu, s0, 31);
        int s1 = v1;
#pragma unroll
        for (int o = 1; o < 32; o <<= 1) {
            int t = __shfl_up_sync(0xffffffffu, s1, o);
            if (lane >= o) s1 += t;
        }
        int b = blockIdx.x;
        int e0 = __shfl_sync(0xffffffffu, s0 - v0, b & 31);
        int e1 = tot0 + __shfl_sync(0xffffffffu, s1 - v1, (b - 32) & 31);
        if (lane == 0) boff_s = (b < 32) ? e0 : e1;
    }
    __syncthreads();
    int i = blockIdx.x * 1024 + tid;
    int v = (i < NN) ? g_cnt[i] : 0;
    int s = v;
#pragma unroll
    for (int o = 1; o < 32; o <<= 1) {
        int t = __shfl_up_sync(0xffffffffu, s, o);
        if (lane >= o) s += t;
    }
    if (lane == 31) ws[wid] = s;
    __syncthreads();
    if (wid == 0) {
        int t = ws[lane];
#pragma unroll
        for (int o = 1; o < 32; o <<= 1) {
            int u = __shfl_up_sync(0xffffffffu, t, o);
            if (lane >= o) t += u;
        }
        ws[lane] = t;
    }
    __syncthreads();
    int excl = s - v + (wid > 0 ? ws[wid - 1] : 0) + boff_s;
    if (i < NN) g_cursor[i] = excl;
}

// fused scatter+gather: one warp per edge; lane 0 claims slot, warp copies row
__global__ void k_scatgath(const float* __restrict__ ea) {
    int wid = threadIdx.x >> 5;
    int lane = threadIdx.x & 31;
    int e = blockIdx.x * 8 + wid;
    if (e >= NE) return;
    int pos;
    if (lane == 0) {
        int d = g_dstv[e];
        pos = atomicAdd(&g_cursor[d], 1);
        g_ssort[pos] = g_src[e];
        g_dsort[pos] = d;
    }
    pos = __shfl_sync(0xffffffffu, pos, 0);
    g_eas[(size_t)pos * ED + lane] = ea[(size_t)e * ED + lane];
}

// ---------------- fused edge-linear + aggregate (proven R10) ----------------
#define EAGG_SMEM ((128 * 36 + 32 * 132 + 128 * 132) * 4)
__global__ void __launch_bounds__(256) k_eagg(const float* __restrict__ We,
                                              const float* __restrict__ be) {
    extern __shared__ float smf[];
    unsigned* As = (unsigned*)smf;
    unsigned* Ws = (unsigned*)smf + 128 * 36;
    float* sOut = smf + 128 * 36 + 32 * 132;

    int tid = threadIdx.x;
    int lane = tid & 31;
    int w = tid >> 5;
    size_t tile0 = (size_t)blockIdx.x * 128;

    for (int i = tid; i < 1024; i += 256) {  // A: 128 edges x 32 feats
        int r = i >> 3, c4 = i & 7;
        size_t ge = tile0 + r;
        float4 v = make_float4(0.f, 0.f, 0.f, 0.f);
        if (ge < NE) v = *(const float4*)(g_eas + ge * ED + c4 * 4);
        unsigned* dst = As + r * 36 + c4 * 4;
        dst[0] = to_tf32(v.x); dst[1] = to_tf32(v.y);
        dst[2] = to_tf32(v.z); dst[3] = to_tf32(v.w);
    }
    for (int i = tid; i < 1024; i += 256) {  // W: 32 x 128
        int k = i >> 5, c4 = i & 31;
        float4 v = *(const float4*)(We + (size_t)k * H + c4 * 4);
        unsigned* dst = Ws + k * 132 + c4 * 4;
        dst[0] = to_tf32(v.x); dst[1] = to_tf32(v.y);
        dst[2] = to_tf32(v.z); dst[3] = to_tf32(v.w);
    }
    __syncthreads();

    int g = lane >> 2;
    int r = lane & 3;
    int row_s = w * 16;

    unsigned a[4][4];
#pragma unroll
    for (int ks = 0; ks < 4; ks++) {
        int k0 = ks * 8;
        a[ks][0] = As[(row_s + g) * 36 + k0 + r];
        a[ks][1] = As[(row_s + g + 8) * 36 + k0 + r];
        a[ks][2] = As[(row_s + g) * 36 + k0 + r + 4];
        a[ks][3] = As[(row_s + g + 8) * 36 + k0 + r + 4];
    }

#pragma unroll
    for (int nt = 0; nt < 16; nt++) {
        int n0 = nt * 8;
        float d[4];
        float2 bb = *(const float2*)(be + n0 + 2 * r);
        d[0] = bb.x; d[1] = bb.y; d[2] = bb.x; d[3] = bb.y;
#pragma unroll
        for (int ks = 0; ks < 4; ks++) {
            int k0 = ks * 8;
            unsigned b0 = Ws[(k0 + r) * 132 + n0 + g];
            unsigned b1 = Ws[(k0 + 4 + r) * 132 + n0 + g];
            MMA_TF32(d, a[ks][0], a[ks][1], a[ks][2], a[ks][3], b0, b1);
        }
        int col = n0 + 2 * r;
        *(float2*)(sOut + (row_s + g) * 132 + col) = make_float2(d[0], d[1]);
        *(float2*)(sOut + (row_s + g + 8) * 132 + col) = make_float2(d[2], d[3]);
    }
    // no block sync: warp w consumes only rows [16w, 16w+16) which it wrote

    size_t j0 = tile0 + (size_t)w * 16;
    int myidx;
    if (lane < 16) {
        size_t j = j0 + lane;
        myidx = (j < NE) ? g_ssort[j] : 0;
    } else {
        size_t j = j0 + lane - 16;
        myidx = (j < NE) ? g_dsort[j] : -1;
    }

    int c0 = lane * 4;
    float4 acc = make_float4(0.f, 0.f, 0.f, 0.f);
#pragma unroll
    for (int i = 0; i < 16; i++) {
        bool valid = (j0 + i < NE);
        int s = __shfl_sync(0xffffffffu, myidx, i);
        int dd = __shfl_sync(0xffffffffu, myidx, 16 + i);
        if (valid) {
            float4 e4 = *(const float4*)(sOut + (w * 16 + i) * 132 + c0);
            float4 h4 = __ldg((const float4*)(g_h + (size_t)s * H + c0));
            acc.x += fmaxf(e4.x + h4.x, 0.f);
            acc.y += fmaxf(e4.y + h4.y, 0.f);
            acc.z += fmaxf(e4.z + h4.z, 0.f);
            acc.w += fmaxf(e4.w + h4.w, 0.f);
            bool last = (i == 15) || (j0 + i + 1 >= NE);
            int dn = last ? -1 : __shfl_sync(0xffffffffu, myidx, 16 + i + 1);
            if (last || dn != dd) {
                float* zp = g_z + (size_t)dd * H + c0;
                atomicAdd(zp + 0, acc.x);
                atomicAdd(zp + 1, acc.y);
                atomicAdd(zp + 2, acc.z);
                atomicAdd(zp + 3, acc.w);
                acc = make_float4(0.f, 0.f, 0.f, 0.f);
            }
        }
    }
}

// ---------------- node MLP GEMM via 3xTF32 tensor cores --------------------
// which==0: g_t = relu(g_z @ W1 + b1); block0 zeroes BN stats
// which==1: g_z2 = g_t @ W2 + b2
// 128x128 tile, K in 4 phases of 32.
// dyn smem: sAhi 128*36 | sAlo 128*36 | sWhi 32*132 | sWlo 32*132 (u32)
#define MLP3_SMEM ((128 * 36 * 2 + 32 * 132 * 2) * 4)
__global__ void __launch_bounds__(256) k_mlpT3(int which, const float* __restrict__ W,
                                               const float* __restrict__ bias) {
    extern __shared__ float smf[];
    unsigned* sAhi = (unsigned*)smf;
    unsigned* sAlo = sAhi + 128 * 36;
    unsigned* sWhi = sAlo + 128 * 36;
    unsigned* sWlo = sWhi + 32 * 132;

    const float* A = which ? g_t : g_z;
    float* C = which ? g_z2 : g_t;
    int tid = threadIdx.x;
    int lane = tid & 31;
    int w = tid >> 5;
    int row0 = blockIdx.x * 128;

    if (which == 0 && blockIdx.x == 0 && tid < H) {
        g_colsum[tid] = 0.f;
        g_colsq[tid] = 0.f;
    }

    int g = lane >> 2;
    int r = lane & 3;
    int row_s = w * 16;

    float d[16][4];
#pragma unroll
    for (int nt = 0; nt < 16; nt++) {
        d[nt][0] = 0.f; d[nt][1] = 0.f; d[nt][2] = 0.f; d[nt][3] = 0.f;
    }

    for (int ph = 0; ph < 4; ph++) {
        int K0 = ph * 32;
        if (ph) __syncthreads();  // protect smem reuse across phases
        for (int i = tid; i < 1024; i += 256) {  // A: 128 rows x 32 cols
            int rr = i >> 3, c4 = i & 7;
            int gr = row0 + rr;
            float4 v = make_float4(0.f, 0.f, 0.f, 0.f);
            if (gr < NN) v = *(const float4*)(A + (size_t)gr * H + K0 + c4 * 4);
            unsigned *dh = sAhi + rr * 36 + c4 * 4, *dl = sAlo + rr * 36 + c4 * 4;
            split_tf32(v.x, dh[0], dl[0]);
            split_tf32(v.y, dh[1], dl[1]);
            split_tf32(v.z, dh[2], dl[2]);
            split_tf32(v.w, dh[3], dl[3]);
        }
        for (int i = tid; i < 1024; i += 256) {  // W: 32 rows x 128 cols
            int k = i >> 5, c4 = i & 31;
            float4 v = *(const float4*)(W + (size_t)(K0 + k) * H + c4 * 4);
            unsigned *dh = sWhi + k * 132 + c4 * 4, *dl = sWlo + k * 132 + c4 * 4;
            split_tf32(v.x, dh[0], dl[0]);
            split_tf32(v.y, dh[1], dl[1]);
            split_tf32(v.z, dh[2], dl[2]);
            split_tf32(v.w, dh[3], dl[3]);
        }
        __syncthreads();

#pragma unroll
        for (int ks = 0; ks < 4; ks++) {
            int k0 = ks * 8;
            unsigned ah0 = sAhi[(row_s + g) * 36 + k0 + r];
            unsigned ah1 = sAhi[(row_s + g + 8) * 36 + k0 + r];
            unsigned ah2 = sAhi[(row_s + g) * 36 + k0 + r + 4];
            unsigned ah3 = sAhi[(row_s + g + 8) * 36 + k0 + r + 4];
            unsigned al0 = sAlo[(row_s + g) * 36 + k0 + r];
            unsigned al1 = sAlo[(row_s + g + 8) * 36 + k0 + r];
            unsigned al2 = sAlo[(row_s + g) * 36 + k0 + r + 4];
            unsigned al3 = sAlo[(row_s + g + 8) * 36 + k0 + r + 4];
#pragma unroll
            for (int nt = 0; nt < 16; nt++) {
                int n0 = nt * 8;
                unsigned bh0 = sWhi[(k0 + r) * 132 + n0 + g];
                unsigned bh1 = sWhi[(k0 + 4 + r) * 132 + n0 + g];
                unsigned bl0 = sWlo[(k0 + r) * 132 + n0 + g];
                unsigned bl1 = sWlo[(k0 + 4 + r) * 132 + n0 + g];
                MMA_TF32(d[nt], ah0, ah1, ah2, ah3, bh0, bh1);
                MMA_TF32(d[nt], al0, al1, al2, al3, bh0, bh1);
                MMA_TF32(d[nt], ah0, ah1, ah2, ah3, bl0, bl1);
            }
        }
    }

    int rowA = row0 + row_s + g;
    int rowB = rowA + 8;
#pragma unroll
    for (int nt = 0; nt < 16; nt++) {
        int col = nt * 8 + 2 * r;
        float2 bb = *(const float2*)(bias + col);
        float o0 = d[nt][0] + bb.x, o1 = d[nt][1] + bb.y;
        float o2 = d[nt][2] + bb.x, o3 = d[nt][3] + bb.y;
        if (which == 0) {
            o0 = fmaxf(o0, 0.f); o1 = fmaxf(o1, 0.f);
            o2 = fmaxf(o2, 0.f); o3 = fmaxf(o3, 0.f);
        }
        if (rowA < NN) *(float2*)(C + (size_t)rowA * H + col) = make_float2(o0, o1);
        if (rowB < NN) *(float2*)(C + (size_t)rowB * H + col) = make_float2(o2, o3);
    }
}

// ---------------- BN stats over g_z2 (standalone) ---------------------------
__global__ void __launch_bounds__(256) k_bnstats() {
    __shared__ float ss[8 * 128], sq[8 * 128];
    int tid = threadIdx.x;
    int tx = tid & 31, ty = tid >> 5;
    int row0 = blockIdx.x * 128;
    float4 s = make_float4(0.f, 0.f, 0.f, 0.f);
    float4 q = make_float4(0.f, 0.f, 0.f, 0.f);
    for (int rr = ty; rr < 128; rr += 8) {
        int gr = row0 + rr;
        if (gr < NN) {
            float4 v = *(const float4*)(g_z2 + (size_t)gr * H + tx * 4);
            s.x += v.x; s.y += v.y; s.z += v.z; s.w += v.w;
            q.x = fmaf(v.x, v.x, q.x); q.y = fmaf(v.y, v.y, q.y);
            q.z = fmaf(v.z, v.z, q.z); q.w = fmaf(v.w, v.w, q.w);
        }
    }
    *(float4*)(ss + ty * 128 + tx * 4) = s;
    *(float4*)(sq + ty * 128 + tx * 4) = q;
    __syncthreads();
    if (tid < 128) {
        float a = 0.f, b = 0.f;
#pragma unroll
        for (int t = 0; t < 8; t++) {
            a += ss[t * 128 + tid];
            b += sq[t * 128 + tid];
        }
        atomicAdd(&g_colsum[tid], a);
        atomicAdd(&g_colsq[tid], b);
    }
}

// ---------------- BN finalize ----------------
__global__ void k_bnfin(const float* __restrict__ gamma,
                        const float* __restrict__ beta) {
    int c = threadIdx.x;
    float mu = g_colsum[c] * (1.f / NN);
    float var = g_colsq[c] * (1.f / NN) - mu * mu;
    float rs = rsqrtf(var + BN_EPS);
    float sc = rs * gamma[c];
    g_scale[c] = sc;
    g_shift[c] = beta[c] - mu * sc;
}

// ---------------- BN apply + relu + residual (writes h and z for next layer)
__global__ void k_post(float* __restrict__ dout, int use_dout) {
    int i = blockIdx.x * blockDim.x + threadIdx.x;
    if (i >= NN * H / 4) return;
    int c4 = i & 31;
    float4 z = ((const float4*)g_z2)[i];
    float4 sc = ((const float4*)g_scale)[c4];
    float4 sh = ((const float4*)g_shift)[c4];
    float4 hr = ((const float4*)g_h)[i];
    float4 o;
    o.x = fmaxf(fmaf(z.x, sc.x, sh.x), 0.f) + RES_SCALE * hr.x;
    o.y = fmaxf(fmaf(z.y, sc.y, sh.y), 0.f) + RES_SCALE * hr.y;
    o.z = fmaxf(fmaf(z.z, sc.z, sh.z), 0.f) + RES_SCALE * hr.z;
    o.w = fmaxf(fmaf(z.w, sc.w, sh.w), 0.f) + RES_SCALE * hr.w;
    if (use_dout) {
        ((float4*)dout)[i] = o;
    } else {
        ((float4*)g_h)[i] = o;
        ((float4*)g_z)[i] = o;  // pre-init next layer's aggregation target
    }
}

// ---------------- launch ----------------
extern "C" void kernel_launch(void* const* d_in, const int* in_sizes, int n_in,
                              void* d_out, int out_size) {
    const float* x = (const float*)d_in[0];
    const int* ei = (const int*)d_in[1];
    const float* ea = (const float*)d_in[2];
    const float* We = (const float*)d_in[3];
    const float* be = (const float*)d_in[4];
    const float* W1 = (const float*)d_in[5];
    const float* b1 = (const float*)d_in[6];
    const float* W2 = (const float*)d_in[7];
    const float* b2 = (const float*)d_in[8];
    const float* gamma = (const float*)d_in[9];
    const float* beta = (const float*)d_in[10];

    cudaFuncSetAttribute(k_eagg, cudaFuncAttributeMaxDynamicSharedMemorySize,
                         EAGG_SMEM);
    cudaFuncSetAttribute(k_mlpT3, cudaFuncAttributeMaxDynamicSharedMemorySize,
                         MLP3_SMEM);

    const int SCAN_BLOCKS = (NN + 1023) / 1024;  // 49
    const int NODE_BLOCKS = (NN + 127) / 128;    // 391

    k_init<<<(NN * H + 255) / 256, 256>>>(x);
    k_prep<<<(NE + 255) / 256, 256>>>(ei);
    k_scanA<<<SCAN_BLOCKS, 1024>>>();
    k_scanBC<<<SCAN_BLOCKS, 1024>>>(SCAN_BLOCKS);
    k_scatgath<<<(NE + 7) / 8, 256>>>(ea);

    for (int l = 0; l < 3; l++) {
        k_eagg<<<(NE + 127) / 128, 256, EAGG_SMEM>>>(We + (size_t)l * ED * H,
                                                     be + (size_t)l * H);
        k_mlpT3<<<NODE_BLOCKS, 256, MLP3_SMEM>>>(0, W1 + (size_t)l * H * H,
                                                 b1 + (size_t)l * H);
        k_mlpT3<<<NODE_BLOCKS, 256, MLP3_SMEM>>>(1, W2 + (size_t)l * H * H,
                                                 b2 + (size_t)l * H);
        k_bnstats<<<NODE_BLOCKS, 256>>>();
        k_bnfin<<<1, 128>>>(gamma + (size_t)l * H, beta + (size_t)l * H);
        k_post<<<(NN * H / 4 + 255) / 256, 256>>>((float*)d_out, l == 2 ? 1 : 0);
    }
}